// round 13
// baseline (speedup 1.0000x reference)
#include <cuda_runtime.h>
#include <cuda_fp16.h>
#include <stdint.h>

#define BATCH 4
#define NH    16
#define TLEN  1024
#define DH    64
#define DVV   128
#define BM    64
#define BN    64
#define NT    256
#define SCALE_L2E 0.18033688011112042f
#define LAMBDA_INIT 0.783605766531604f
#define RMS_EPS 1e-6f

#define KSTR  144
#define VSTR  272

#define KN (BATCH * 2 * NH * TLEN * DH)
#define VN (BATCH * NH * TLEN * DVV)

__device__ __align__(16) static unsigned int g_khi[KN / 2];
__device__ __align__(16) static unsigned int g_vhi[VN / 2];

#define OFF_Q1   0
#define OFF_Q2   9216
#define OFF_STG  18432
#define STG_SZ   35840
#define STG_K1   0
#define STG_K2   9216
#define STG_V    18432
#define OFF_LAM  90112
#define OFF_SP   90128
#define OFF_SCL  91152
#define SMEM_TOTAL 91648
#define OFF_YB1  0
#define OFF_YB2  36864

__device__ __forceinline__ uint32_t smem_u32(const void* p) {
    uint32_t a;
    asm("{ .reg .u64 t; cvta.to.shared.u64 t, %1; cvt.u32.u64 %0, t; }" : "=r"(a) : "l"(p));
    return a;
}
__device__ __forceinline__ void cp_async16(uint32_t dst, const void* src) {
    asm volatile("cp.async.cg.shared.global [%0], [%1], 16;" :: "r"(dst), "l"(src));
}
__device__ __forceinline__ void cp_commit() { asm volatile("cp.async.commit_group;"); }
__device__ __forceinline__ void cp_wait0()  { asm volatile("cp.async.wait_group 0;" ::: "memory"); }

__device__ __forceinline__ void ldsm4(uint32_t* r, uint32_t a) {
    asm volatile("ldmatrix.sync.aligned.m8n8.x4.shared.b16 {%0,%1,%2,%3}, [%4];"
        : "=r"(r[0]), "=r"(r[1]), "=r"(r[2]), "=r"(r[3]) : "r"(a));
}
__device__ __forceinline__ void ldsm4t(uint32_t* r, uint32_t a) {
    asm volatile("ldmatrix.sync.aligned.m8n8.x4.trans.shared.b16 {%0,%1,%2,%3}, [%4];"
        : "=r"(r[0]), "=r"(r[1]), "=r"(r[2]), "=r"(r[3]) : "r"(a));
}
__device__ __forceinline__ void mma16816(float* c, const uint32_t* a,
                                         uint32_t b0, uint32_t b1) {
    asm volatile(
        "mma.sync.aligned.m16n8k16.row.col.f32.f16.f16.f32 "
        "{%0,%1,%2,%3}, {%4,%5,%6,%7}, {%8,%9}, {%0,%1,%2,%3};"
        : "+f"(c[0]), "+f"(c[1]), "+f"(c[2]), "+f"(c[3])
        : "r"(a[0]), "r"(a[1]), "r"(a[2]), "r"(a[3]), "r"(b0), "r"(b1));
}
__device__ __forceinline__ uint32_t packf(float a, float b) {
    __half2 h = __floats2half2_rn(a, b);
    return *reinterpret_cast<uint32_t*>(&h);
}
__device__ __forceinline__ float ex2(float x) {
    float y;
    asm("ex2.approx.f32 %0, %1;" : "=f"(y) : "f"(x));
    return y;
}

// ======================= precompute: K/V -> fp16 (16B stores) =======================
__global__ __launch_bounds__(256)
void conv_kv(const float* __restrict__ k, const float* __restrict__ v)
{
    const int KN8 = KN / 8, VN8 = VN / 8;
    for (int i = blockIdx.x * blockDim.x + threadIdx.x; i < KN8 + VN8;
         i += gridDim.x * blockDim.x) {
        if (i < KN8) {
            float4 x0 = ((const float4*)k)[2 * i];
            float4 x1 = ((const float4*)k)[2 * i + 1];
            uint4 o;
            o.x = packf(x0.x, x0.y); o.y = packf(x0.z, x0.w);
            o.z = packf(x1.x, x1.y); o.w = packf(x1.z, x1.w);
            ((uint4*)g_khi)[i] = o;
        } else {
            int j = i - KN8;
            float4 x0 = ((const float4*)v)[2 * j];
            float4 x1 = ((const float4*)v)[2 * j + 1];
            uint4 o;
            o.x = packf(x0.x, x0.y); o.y = packf(x0.z, x0.w);
            o.z = packf(x1.x, x1.y); o.w = packf(x1.z, x1.w);
            ((uint4*)g_vhi)[j] = o;
        }
    }
}

// ======================= attention =======================
__global__ __launch_bounds__(NT, 2)
void diff_attn_hmma11(const float* __restrict__ q,
                      const float* __restrict__ lq1,
                      const float* __restrict__ lk1,
                      const float* __restrict__ lq2,
                      const float* __restrict__ lk2,
                      const float* __restrict__ w,
                      float* __restrict__ out)
{
    extern __shared__ char smem[];
    const uint32_t sb = smem_u32(smem);

    const int qt = (int)(gridDim.x - 1u - blockIdx.x);   // big tiles first
    const int h  = blockIdx.y;
    const int b  = blockIdx.z;
    const int t    = threadIdx.x;
    const int warp = t >> 5;
    const int lane = t & 31;
    const int hd   = warp >> 2;
    const int r0   = (warp & 3) * 16;
    const int g    = lane >> 2;
    const int tq   = lane & 3;
    const int l8   = lane & 7;
    const int qq1  = (lane >> 3) & 1;
    const int qq2  = lane >> 4;
    const int wodd = warp & 1;           // phase-stagger selector

    const uint32_t a_off  = (uint32_t)((r0 + qq1 * 8 + l8) * KSTR + qq2 * 16);
    const uint32_t bk_off = (uint32_t)((qq2 * 8 + l8) * KSTR + qq1 * 16);
    const uint32_t bv_off = (uint32_t)((qq1 * 8 + l8) * VSTR + qq2 * 16);

    const size_t kbase = ((size_t)b * 2 * NH + 2 * h) * TLEN * DH;
    const size_t vbase = ((size_t)b * NH + h) * TLEN * DVV;
    const int ntiles = qt + 1;

    const char* gk1 = (const char*)g_khi + kbase * 2;
    const char* gk2 = gk1 + (size_t)TLEN * DH * 2;
    const char* gv  = (const char*)g_vhi + vbase * 2;

    // ---- prefetch stage 0 ----
    {
        const uint32_t dst = sb + OFF_STG;
        #pragma unroll
        for (int j = 0; j < 4; j++) {
            int c = t + j * NT;
            int ten = c >> 9, row = (c >> 3) & 63, col = c & 7;
            const char* src = ten ? gk2 : gk1;
            cp_async16(dst + ten * 9216 + row * KSTR + col * 16,
                       src + row * 128 + col * 16);
        }
        #pragma unroll
        for (int j = 0; j < 4; j++) {
            int c = t + j * NT;
            int row = c >> 4, col = c & 15;
            cp_async16(dst + STG_V + row * VSTR + col * 16,
                       gv + row * 256 + col * 16);
        }
        cp_commit();
    }

    if (t == 0) {
        float s1 = 0.f, s2 = 0.f;
        #pragma unroll 8
        for (int d = 0; d < DH; d++) {
            s1 += lq1[h * DH + d] * lk1[h * DH + d];
            s2 += lq2[h * DH + d] * lk2[h * DH + d];
        }
        *(float*)(smem + OFF_LAM) = __expf(s1) - __expf(s2) + LAMBDA_INIT;
    }

    // ---- Q convert (fold SCALING*log2e) ----
    {
        const float* qg1 = q + kbase + (size_t)qt * BM * DH;
        const float* qg2 = qg1 + (size_t)TLEN * DH;
        #pragma unroll
        for (int jj = 0; jj < 8; jj++) {
            int i = t + jj * NT;
            int r = i >> 5, d2 = i & 31;
            float2 x1 = ((const float2*)qg1)[i];
            *(uint32_t*)(smem + OFF_Q1 + r * KSTR + d2 * 4) =
                packf(x1.x * SCALE_L2E, x1.y * SCALE_L2E);
            float2 x2 = ((const float2*)qg2)[i];
            *(uint32_t*)(smem + OFF_Q2 + r * KSTR + d2 * 4) =
                packf(x2.x * SCALE_L2E, x2.y * SCALE_L2E);
        }
    }
    __syncthreads();

    uint32_t qf[4][4];
    {
        const uint32_t sb_q = sb + (hd ? OFF_Q2 : OFF_Q1);
        #pragma unroll
        for (int kc = 0; kc < 4; kc++)
            ldsm4(qf[kc], sb_q + kc * 32 + a_off);
    }

    float yacc[16][4];
    #pragma unroll
    for (int nt = 0; nt < 16; nt++)
        #pragma unroll
        for (int j = 0; j < 4; j++) yacc[nt][j] = 0.f;
    float l_lo = 0.f, l_hi = 0.f;

    const int rowg = qt * BM + r0 + g;
    const int rowh = rowg + 8;

    for (int kt = 0; kt < ntiles; kt++) {
        const uint32_t stg = sb + OFF_STG + (uint32_t)(kt & 1) * STG_SZ;
        cp_wait0();
        __syncthreads();

        if (kt + 1 < ntiles) {
            const uint32_t dst = sb + OFF_STG + (uint32_t)((kt + 1) & 1) * STG_SZ;
            const size_t ko = (size_t)(kt + 1) * BN * DH * 2;
            const size_t vo = (size_t)(kt + 1) * BN * DVV * 2;
            #pragma unroll
            for (int j = 0; j < 4; j++) {
                int c = t + j * NT;
                int ten = c >> 9, row = (c >> 3) & 63, col = c & 7;
                const char* src = (ten ? gk2 : gk1) + ko;
                cp_async16(dst + ten * 9216 + row * KSTR + col * 16,
                           src + row * 128 + col * 16);
            }
            #pragma unroll
            for (int j = 0; j < 4; j++) {
                int c = t + j * NT;
                int row = c >> 4, col = c & 15;
                cp_async16(dst + STG_V + row * VSTR + col * 16,
                           gv + vo + row * 256 + col * 16);
            }
            cp_commit();
        }

        const uint32_t sb_k = stg + (hd ? STG_K2 : STG_K1);
        const uint32_t sb_v = stg + STG_V;
        const int kb = kt * BN;
        const bool diag = (kt == qt);

        // ---- two 32-key halves; odd warps take half 1 first (phase stagger) ----
        #pragma unroll
        for (int hh = 0; hh < 2; hh++) {
            const int half = hh ^ wodd;
            const int kb2  = kb + half * 32;

            // QK (pipelined ldsm over kc)
            float S[4][4];
            #pragma unroll
            for (int nt = 0; nt < 4; nt++)
                #pragma unroll
                for (int j = 0; j < 4; j++) S[nt][j] = 0.f;

            #pragma unroll
            for (int aa = 0; aa < 2; aa++) {
                const int a = 2 * half + aa;
                const uint32_t base = sb_k + (uint32_t)(a * 16 * KSTR) + bk_off;
                uint32_t bh[2][4];
                ldsm4(bh[0], base);
                #pragma unroll
                for (int kc = 0; kc < 4; kc++) {
                    if (kc < 3) ldsm4(bh[(kc + 1) & 1], base + (kc + 1) * 32);
                    mma16816(S[2 * aa],     qf[kc], bh[kc & 1][0], bh[kc & 1][1]);
                    mma16816(S[2 * aa + 1], qf[kc], bh[kc & 1][2], bh[kc & 1][3]);
                }
            }

            // mask + exp2 + pack
            uint32_t Pa[4], Pb[4];
            if (diag) {
                #pragma unroll
                for (int nt = 0; nt < 4; nt++) {
                    int c0 = kb2 + nt * 8 + tq * 2;
                    float p0 = (c0     > rowg) ? 0.f : ex2(S[nt][0]);
                    float p1 = (c0 + 1 > rowg) ? 0.f : ex2(S[nt][1]);
                    float p2 = (c0     > rowh) ? 0.f : ex2(S[nt][2]);
                    float p3 = (c0 + 1 > rowh) ? 0.f : ex2(S[nt][3]);
                    l_lo += p0 + p1;  l_hi += p2 + p3;
                    Pa[nt] = packf(p0, p1);
                    Pb[nt] = packf(p2, p3);
                }
            } else {
                #pragma unroll
                for (int nt = 0; nt < 4; nt++) {
                    float p0 = ex2(S[nt][0]);
                    float p1 = ex2(S[nt][1]);
                    float p2 = ex2(S[nt][2]);
                    float p3 = ex2(S[nt][3]);
                    l_lo += p0 + p1;  l_hi += p2 + p3;
                    Pa[nt] = packf(p0, p1);
                    Pb[nt] = packf(p2, p3);
                }
            }

            // PV (non-pipelined — measured best at the 128-reg cliff)
            #pragma unroll
            for (int kc2 = 0; kc2 < 2; kc2++) {
                const int kc = 2 * half + kc2;
                uint32_t ah[4] = { Pa[2 * kc2], Pb[2 * kc2],
                                   Pa[2 * kc2 + 1], Pb[2 * kc2 + 1] };
                const uint32_t vb = sb_v + (uint32_t)(kc * 16 * VSTR) + bv_off;
                #pragma unroll
                for (int a = 0; a < 8; a++) {
                    uint32_t bh[4];
                    ldsm4t(bh, vb + a * 32);
                    mma16816(yacc[2 * a],     ah, bh[0], bh[1]);
                    mma16816(yacc[2 * a + 1], ah, bh[2], bh[3]);
                }
            }
        }
    }

    // ---- epilogue ----
    l_lo += __shfl_xor_sync(0xFFFFFFFF, l_lo, 1);
    l_lo += __shfl_xor_sync(0xFFFFFFFF, l_lo, 2);
    l_hi += __shfl_xor_sync(0xFFFFFFFF, l_hi, 1);
    l_hi += __shfl_xor_sync(0xFFFFFFFF, l_hi, 2);
    const float inv_lo = 1.f / l_lo;
    const float inv_hi = 1.f / l_hi;
    const float lam = *(const float*)(smem + OFF_LAM);

    __syncthreads();

    float* yb = (float*)(smem + (hd ? OFF_YB2 : OFF_YB1));
    const int rg = r0 + g, rh = r0 + g + 8;
    #pragma unroll
    for (int nt = 0; nt < 16; nt++) {
        int c = nt * 8 + tq * 2;
        yb[rg * 132 + c]     = yacc[nt][0] * inv_lo;
        yb[rg * 132 + c + 1] = yacc[nt][1] * inv_lo;
        yb[rh * 132 + c]     = yacc[nt][2] * inv_hi;
        yb[rh * 132 + c + 1] = yacc[nt][3] * inv_hi;
    }
    __syncthreads();

    float* yb1 = (float*)(smem + OFF_YB1);
    float* yb2 = (float*)(smem + OFF_YB2);
    float* sp  = (float*)(smem + OFF_SP);
    float* scl = (float*)(smem + OFF_SCL);

    const int rr  = t >> 2;
    const int cc0 = (t & 3) * 32;
    float ssq = 0.f;
    #pragma unroll 8
    for (int j = 0; j < 32; j += 4) {
        float4 y1 = *(float4*)&yb1[rr * 132 + cc0 + j];
        float4 y2 = *(float4*)&yb2[rr * 132 + cc0 + j];
        float4 y;
        y.x = y1.x - lam * y2.x;  y.y = y1.y - lam * y2.y;
        y.z = y1.z - lam * y2.z;  y.w = y1.w - lam * y2.w;
        ssq += y.x * y.x + y.y * y.y + y.z * y.z + y.w * y.w;
        *(float4*)&yb1[rr * 132 + cc0 + j] = y;
    }
    sp[(t & 3) * 64 + rr] = ssq;
    __syncthreads();
    if (t < 64) {
        float tot = sp[t] + sp[64 + t] + sp[128 + t] + sp[192 + t];
        scl[t] = rsqrtf(tot * (1.f / (float)DVV) + RMS_EPS) * (1.f - LAMBDA_INIT);
    }
    __syncthreads();

    const float sc = scl[rr];
    float* og = out + (((size_t)b * NH + h) * TLEN + (size_t)qt * BM + rr) * DVV + cc0;
    #pragma unroll 8
    for (int j = 0; j < 32; j += 4) {
        float4 y = *(float4*)&yb1[rr * 132 + cc0 + j];
        float4 wv = *(const float4*)&w[cc0 + j];
        y.x *= sc * wv.x;  y.y *= sc * wv.y;
        y.z *= sc * wv.z;  y.w *= sc * wv.w;
        *(float4*)&og[j] = y;
    }
}

extern "C" void kernel_launch(void* const* d_in, const int* in_sizes, int n_in,
                              void* d_out, int out_size)
{
    const float* q   = (const float*)d_in[0];
    const float* k   = (const float*)d_in[1];
    const float* v   = (const float*)d_in[2];
    const float* lq1 = (const float*)d_in[4];
    const float* lk1 = (const float*)d_in[5];
    const float* lq2 = (const float*)d_in[6];
    const float* lk2 = (const float*)d_in[7];
    const float* w   = (const float*)d_in[8];
    float* out = (float*)d_out;

    static int attr_set = 0;
    if (!attr_set) {
        cudaFuncSetAttribute(diff_attn_hmma11,
                             cudaFuncAttributeMaxDynamicSharedMemorySize, SMEM_TOTAL);
        attr_set = 1;
    }

    conv_kv<<<2048, 256>>>(k, v);
    dim3 grid(TLEN / BM, NH, BATCH);
    diff_attn_hmma11<<<grid, NT, SMEM_TOTAL>>>(q, lq1, lk1, lq2, lk2, w, out);
}

// round 14
// speedup vs baseline: 1.0154x; 1.0154x over previous
#include <cuda_runtime.h>
#include <cuda_fp16.h>
#include <stdint.h>

#define BATCH 4
#define NH    16
#define TLEN  1024
#define DH    64
#define DVV   128
#define BM    64
#define BN    64
#define NT    256
#define SCALE_L2E 0.18033688011112042f
#define LAMBDA_INIT 0.783605766531604f
#define RMS_EPS 1e-6f

#define KSTR  144
#define VSTR  272

#define KN (BATCH * 2 * NH * TLEN * DH)
#define VN (BATCH * NH * TLEN * DVV)

__device__ __align__(16) static unsigned int g_khi[KN / 2];
__device__ __align__(16) static unsigned int g_vhi[VN / 2];
__device__ static float g_lam[NH];

#define OFF_Q1   0
#define OFF_Q2   9216
#define OFF_STG  18432
#define STG_SZ   35840
#define STG_K1   0
#define STG_K2   9216
#define STG_V    18432
#define OFF_SP   90112
#define OFF_SCL  91136
#define SMEM_TOTAL 91648
#define OFF_YB1  0
#define OFF_YB2  36864

__device__ __forceinline__ uint32_t smem_u32(const void* p) {
    uint32_t a;
    asm("{ .reg .u64 t; cvta.to.shared.u64 t, %1; cvt.u32.u64 %0, t; }" : "=r"(a) : "l"(p));
    return a;
}
__device__ __forceinline__ void cp_async16(uint32_t dst, const void* src) {
    asm volatile("cp.async.cg.shared.global [%0], [%1], 16;" :: "r"(dst), "l"(src));
}
__device__ __forceinline__ void cp_commit() { asm volatile("cp.async.commit_group;"); }
__device__ __forceinline__ void cp_wait0()  { asm volatile("cp.async.wait_group 0;" ::: "memory"); }

__device__ __forceinline__ void ldsm4(uint32_t* r, uint32_t a) {
    asm volatile("ldmatrix.sync.aligned.m8n8.x4.shared.b16 {%0,%1,%2,%3}, [%4];"
        : "=r"(r[0]), "=r"(r[1]), "=r"(r[2]), "=r"(r[3]) : "r"(a));
}
__device__ __forceinline__ void ldsm4t(uint32_t* r, uint32_t a) {
    asm volatile("ldmatrix.sync.aligned.m8n8.x4.trans.shared.b16 {%0,%1,%2,%3}, [%4];"
        : "=r"(r[0]), "=r"(r[1]), "=r"(r[2]), "=r"(r[3]) : "r"(a));
}
__device__ __forceinline__ void mma16816(float* c, const uint32_t* a,
                                         uint32_t b0, uint32_t b1) {
    asm volatile(
        "mma.sync.aligned.m16n8k16.row.col.f32.f16.f16.f32 "
        "{%0,%1,%2,%3}, {%4,%5,%6,%7}, {%8,%9}, {%0,%1,%2,%3};"
        : "+f"(c[0]), "+f"(c[1]), "+f"(c[2]), "+f"(c[3])
        : "r"(a[0]), "r"(a[1]), "r"(a[2]), "r"(a[3]), "r"(b0), "r"(b1));
}
__device__ __forceinline__ uint32_t packf(float a, float b) {
    __half2 h = __floats2half2_rn(a, b);
    return *reinterpret_cast<uint32_t*>(&h);
}
__device__ __forceinline__ float ex2(float x) {
    float y;
    asm("ex2.approx.f32 %0, %1;" : "=f"(y) : "f"(x));
    return y;
}

// ======= precompute: K/V -> fp16 (16B stores) + per-head lambda =======
__global__ __launch_bounds__(256)
void conv_kv(const float* __restrict__ k, const float* __restrict__ v,
             const float* __restrict__ lq1, const float* __restrict__ lk1,
             const float* __restrict__ lq2, const float* __restrict__ lk2)
{
    if (blockIdx.x == 0 && threadIdx.x < NH) {
        const int h = threadIdx.x;
        float s1 = 0.f, s2 = 0.f;
        #pragma unroll 8
        for (int d = 0; d < DH; d++) {
            s1 += lq1[h * DH + d] * lk1[h * DH + d];
            s2 += lq2[h * DH + d] * lk2[h * DH + d];
        }
        g_lam[h] = __expf(s1) - __expf(s2) + LAMBDA_INIT;
    }

    const int KN8 = KN / 8, VN8 = VN / 8;
    for (int i = blockIdx.x * blockDim.x + threadIdx.x; i < KN8 + VN8;
         i += gridDim.x * blockDim.x) {
        if (i < KN8) {
            float4 x0 = ((const float4*)k)[2 * i];
            float4 x1 = ((const float4*)k)[2 * i + 1];
            uint4 o;
            o.x = packf(x0.x, x0.y); o.y = packf(x0.z, x0.w);
            o.z = packf(x1.x, x1.y); o.w = packf(x1.z, x1.w);
            ((uint4*)g_khi)[i] = o;
        } else {
            int j = i - KN8;
            float4 x0 = ((const float4*)v)[2 * j];
            float4 x1 = ((const float4*)v)[2 * j + 1];
            uint4 o;
            o.x = packf(x0.x, x0.y); o.y = packf(x0.z, x0.w);
            o.z = packf(x1.x, x1.y); o.w = packf(x1.z, x1.w);
            ((uint4*)g_vhi)[j] = o;
        }
    }
}

// ======================= attention =======================
__global__ __launch_bounds__(NT, 2)
void diff_attn_hmma12(const float* __restrict__ q,
                      const float* __restrict__ w,
                      float* __restrict__ out)
{
    extern __shared__ char smem[];
    const uint32_t sb = smem_u32(smem);

    const int qt = (int)(gridDim.x - 1u - blockIdx.x);   // big tiles first
    const int h  = blockIdx.y;
    const int b  = blockIdx.z;
    const int t    = threadIdx.x;
    const int warp = t >> 5;
    const int lane = t & 31;
    const int hd   = warp >> 2;
    const int r0   = (warp & 3) * 16;
    const int g    = lane >> 2;
    const int tq   = lane & 3;
    const int l8   = lane & 7;
    const int qq1  = (lane >> 3) & 1;
    const int qq2  = lane >> 4;
    const int wodd = warp & 1;           // phase-stagger selector

    const uint32_t a_off  = (uint32_t)((r0 + qq1 * 8 + l8) * KSTR + qq2 * 16);
    const uint32_t bk_off = (uint32_t)((qq2 * 8 + l8) * KSTR + qq1 * 16);
    const uint32_t bv_off = (uint32_t)((qq1 * 8 + l8) * VSTR + qq2 * 16);

    const size_t kbase = ((size_t)b * 2 * NH + 2 * h) * TLEN * DH;
    const size_t vbase = ((size_t)b * NH + h) * TLEN * DVV;
    const int ntiles = qt + 1;

    const char* gk1 = (const char*)g_khi + kbase * 2;
    const char* gk2 = gk1 + (size_t)TLEN * DH * 2;
    const char* gv  = (const char*)g_vhi + vbase * 2;

    // ---- prefetch stage 0 ----
    {
        const uint32_t dst = sb + OFF_STG;
        #pragma unroll
        for (int j = 0; j < 4; j++) {
            int c = t + j * NT;
            int ten = c >> 9, row = (c >> 3) & 63, col = c & 7;
            const char* src = ten ? gk2 : gk1;
            cp_async16(dst + ten * 9216 + row * KSTR + col * 16,
                       src + row * 128 + col * 16);
        }
        #pragma unroll
        for (int j = 0; j < 4; j++) {
            int c = t + j * NT;
            int row = c >> 4, col = c & 15;
            cp_async16(dst + STG_V + row * VSTR + col * 16,
                       gv + row * 256 + col * 16);
        }
        cp_commit();
    }

    // ---- Q convert (fold SCALING*log2e) ----
    {
        const float* qg1 = q + kbase + (size_t)qt * BM * DH;
        const float* qg2 = qg1 + (size_t)TLEN * DH;
        #pragma unroll
        for (int jj = 0; jj < 8; jj++) {
            int i = t + jj * NT;
            int r = i >> 5, d2 = i & 31;
            float2 x1 = ((const float2*)qg1)[i];
            *(uint32_t*)(smem + OFF_Q1 + r * KSTR + d2 * 4) =
                packf(x1.x * SCALE_L2E, x1.y * SCALE_L2E);
            float2 x2 = ((const float2*)qg2)[i];
            *(uint32_t*)(smem + OFF_Q2 + r * KSTR + d2 * 4) =
                packf(x2.x * SCALE_L2E, x2.y * SCALE_L2E);
        }
    }
    __syncthreads();

    uint32_t qf[4][4];
    {
        const uint32_t sb_q = sb + (hd ? OFF_Q2 : OFF_Q1);
        #pragma unroll
        for (int kc = 0; kc < 4; kc++)
            ldsm4(qf[kc], sb_q + kc * 32 + a_off);
    }

    float yacc[16][4];
    #pragma unroll
    for (int nt = 0; nt < 16; nt++)
        #pragma unroll
        for (int j = 0; j < 4; j++) yacc[nt][j] = 0.f;
    float l_lo = 0.f, l_hi = 0.f;

    const int rowg = qt * BM + r0 + g;
    const int rowh = rowg + 8;

    for (int kt = 0; kt < ntiles; kt++) {
        const uint32_t stg = sb + OFF_STG + (uint32_t)(kt & 1) * STG_SZ;
        cp_wait0();
        __syncthreads();

        if (kt + 1 < ntiles) {
            const uint32_t dst = sb + OFF_STG + (uint32_t)((kt + 1) & 1) * STG_SZ;
            const size_t ko = (size_t)(kt + 1) * BN * DH * 2;
            const size_t vo = (size_t)(kt + 1) * BN * DVV * 2;
            #pragma unroll
            for (int j = 0; j < 4; j++) {
                int c = t + j * NT;
                int ten = c >> 9, row = (c >> 3) & 63, col = c & 7;
                const char* src = (ten ? gk2 : gk1) + ko;
                cp_async16(dst + ten * 9216 + row * KSTR + col * 16,
                           src + row * 128 + col * 16);
            }
            #pragma unroll
            for (int j = 0; j < 4; j++) {
                int c = t + j * NT;
                int row = c >> 4, col = c & 15;
                cp_async16(dst + STG_V + row * VSTR + col * 16,
                           gv + vo + row * 256 + col * 16);
            }
            cp_commit();
        }

        const uint32_t sb_k = stg + (hd ? STG_K2 : STG_K1);
        const uint32_t sb_v = stg + STG_V;
        const int kb = kt * BN;
        const bool diag = (kt == qt);

        // ---- two 32-key halves; odd warps take half 1 first (phase stagger) ----
        #pragma unroll
        for (int hh = 0; hh < 2; hh++) {
            const int half = hh ^ wodd;
            const int kb2  = kb + half * 32;

            // QK (pipelined ldsm over kc)
            float S[4][4];
            #pragma unroll
            for (int nt = 0; nt < 4; nt++)
                #pragma unroll
                for (int j = 0; j < 4; j++) S[nt][j] = 0.f;

            #pragma unroll
            for (int aa = 0; aa < 2; aa++) {
                const int a = 2 * half + aa;
                const uint32_t base = sb_k + (uint32_t)(a * 16 * KSTR) + bk_off;
                uint32_t bh[2][4];
                ldsm4(bh[0], base);
                #pragma unroll
                for (int kc = 0; kc < 4; kc++) {
                    if (kc < 3) ldsm4(bh[(kc + 1) & 1], base + (kc + 1) * 32);
                    mma16816(S[2 * aa],     qf[kc], bh[kc & 1][0], bh[kc & 1][1]);
                    mma16816(S[2 * aa + 1], qf[kc], bh[kc & 1][2], bh[kc & 1][3]);
                }
            }

            // mask + exp2 + pack
            uint32_t Pa[4], Pb[4];
            if (diag) {
                #pragma unroll
                for (int nt = 0; nt < 4; nt++) {
                    int c0 = kb2 + nt * 8 + tq * 2;
                    float p0 = (c0     > rowg) ? 0.f : ex2(S[nt][0]);
                    float p1 = (c0 + 1 > rowg) ? 0.f : ex2(S[nt][1]);
                    float p2 = (c0     > rowh) ? 0.f : ex2(S[nt][2]);
                    float p3 = (c0 + 1 > rowh) ? 0.f : ex2(S[nt][3]);
                    l_lo += p0 + p1;  l_hi += p2 + p3;
                    Pa[nt] = packf(p0, p1);
                    Pb[nt] = packf(p2, p3);
                }
            } else {
                #pragma unroll
                for (int nt = 0; nt < 4; nt++) {
                    float p0 = ex2(S[nt][0]);
                    float p1 = ex2(S[nt][1]);
                    float p2 = ex2(S[nt][2]);
                    float p3 = ex2(S[nt][3]);
                    l_lo += p0 + p1;  l_hi += p2 + p3;
                    Pa[nt] = packf(p0, p1);
                    Pb[nt] = packf(p2, p3);
                }
            }

            // PV (non-pipelined — measured best at the 128-reg cliff)
            #pragma unroll
            for (int kc2 = 0; kc2 < 2; kc2++) {
                const int kc = 2 * half + kc2;
                uint32_t ah[4] = { Pa[2 * kc2], Pb[2 * kc2],
                                   Pa[2 * kc2 + 1], Pb[2 * kc2 + 1] };
                const uint32_t vb = sb_v + (uint32_t)(kc * 16 * VSTR) + bv_off;
                #pragma unroll
                for (int a = 0; a < 8; a++) {
                    uint32_t bh[4];
                    ldsm4t(bh, vb + a * 32);
                    mma16816(yacc[2 * a],     ah, bh[0], bh[1]);
                    mma16816(yacc[2 * a + 1], ah, bh[2], bh[3]);
                }
            }
        }
    }

    // ---- epilogue ----
    l_lo += __shfl_xor_sync(0xFFFFFFFF, l_lo, 1);
    l_lo += __shfl_xor_sync(0xFFFFFFFF, l_lo, 2);
    l_hi += __shfl_xor_sync(0xFFFFFFFF, l_hi, 1);
    l_hi += __shfl_xor_sync(0xFFFFFFFF, l_hi, 2);
    const float inv_lo = 1.f / l_lo;
    const float inv_hi = 1.f / l_hi;
    const float lam = g_lam[h];

    __syncthreads();

    float* yb = (float*)(smem + (hd ? OFF_YB2 : OFF_YB1));
    const int rg = r0 + g, rh = r0 + g + 8;
    #pragma unroll
    for (int nt = 0; nt < 16; nt++) {
        int c = nt * 8 + tq * 2;
        yb[rg * 132 + c]     = yacc[nt][0] * inv_lo;
        yb[rg * 132 + c + 1] = yacc[nt][1] * inv_lo;
        yb[rh * 132 + c]     = yacc[nt][2] * inv_hi;
        yb[rh * 132 + c + 1] = yacc[nt][3] * inv_hi;
    }
    __syncthreads();

    float* yb1 = (float*)(smem + OFF_YB1);
    float* yb2 = (float*)(smem + OFF_YB2);
    float* sp  = (float*)(smem + OFF_SP);
    float* scl = (float*)(smem + OFF_SCL);

    const int rr  = t >> 2;
    const int cc0 = (t & 3) * 32;
    float ssq = 0.f;
    #pragma unroll 8
    for (int j = 0; j < 32; j += 4) {
        float4 y1 = *(float4*)&yb1[rr * 132 + cc0 + j];
        float4 y2 = *(float4*)&yb2[rr * 132 + cc0 + j];
        float4 y;
        y.x = y1.x - lam * y2.x;  y.y = y1.y - lam * y2.y;
        y.z = y1.z - lam * y2.z;  y.w = y1.w - lam * y2.w;
        ssq += y.x * y.x + y.y * y.y + y.z * y.z + y.w * y.w;
        *(float4*)&yb1[rr * 132 + cc0 + j] = y;
    }
    sp[(t & 3) * 64 + rr] = ssq;
    __syncthreads();
    if (t < 64) {
        float tot = sp[t] + sp[64 + t] + sp[128 + t] + sp[192 + t];
        scl[t] = rsqrtf(tot * (1.f / (float)DVV) + RMS_EPS) * (1.f - LAMBDA_INIT);
    }
    __syncthreads();

    const float sc = scl[rr];
    float* og = out + (((size_t)b * NH + h) * TLEN + (size_t)qt * BM + rr) * DVV + cc0;
    #pragma unroll 8
    for (int j = 0; j < 32; j += 4) {
        float4 y = *(float4*)&yb1[rr * 132 + cc0 + j];
        float4 wv = *(const float4*)&w[cc0 + j];
        y.x *= sc * wv.x;  y.y *= sc * wv.y;
        y.z *= sc * wv.z;  y.w *= sc * wv.w;
        *(float4*)&og[j] = y;
    }
}

extern "C" void kernel_launch(void* const* d_in, const int* in_sizes, int n_in,
                              void* d_out, int out_size)
{
    const float* q   = (const float*)d_in[0];
    const float* k   = (const float*)d_in[1];
    const float* v   = (const float*)d_in[2];
    const float* lq1 = (const float*)d_in[4];
    const float* lk1 = (const float*)d_in[5];
    const float* lq2 = (const float*)d_in[6];
    const float* lk2 = (const float*)d_in[7];
    const float* w   = (const float*)d_in[8];
    float* out = (float*)d_out;

    static int attr_set = 0;
    if (!attr_set) {
        cudaFuncSetAttribute(diff_attn_hmma12,
                             cudaFuncAttributeMaxDynamicSharedMemorySize, SMEM_TOTAL);
        attr_set = 1;
    }

    conv_kv<<<1184, 256>>>(k, v, lq1, lk1, lq2, lk2);
    dim3 grid(TLEN / BM, NH, BATCH);
    diff_attn_hmma12<<<grid, NT, SMEM_TOTAL>>>(q, w, out);
}

// round 15
// speedup vs baseline: 1.0271x; 1.0115x over previous
#include <cuda_runtime.h>
#include <cuda_fp16.h>
#include <stdint.h>

#define BATCH 4
#define NH    16
#define TLEN  1024
#define DH    64
#define DVV   128
#define BM    64
#define BN    64
#define NT    256
#define SCALE_L2E 0.18033688011112042f
#define LAMBDA_INIT 0.783605766531604f
#define RMS_EPS 1e-6f

#define KSTR  144
#define VSTR  272

#define KN (BATCH * 2 * NH * TLEN * DH)
#define VN (BATCH * NH * TLEN * DVV)

__device__ __align__(16) static unsigned int g_khi[KN / 2];
__device__ __align__(16) static unsigned int g_vhi[VN / 2];
__device__ static float g_lam[NH];

#define OFF_Q1   0
#define OFF_Q2   9216
#define OFF_STG  18432
#define STG_SZ   35840
#define STG_K1   0
#define STG_K2   9216
#define STG_V    18432
#define OFF_SP   90112
#define OFF_SCL  91136
#define SMEM_TOTAL 91648
#define OFF_YB1  0
#define OFF_YB2  36864

__device__ __forceinline__ uint32_t smem_u32(const void* p) {
    uint32_t a;
    asm("{ .reg .u64 t; cvta.to.shared.u64 t, %1; cvt.u32.u64 %0, t; }" : "=r"(a) : "l"(p));
    return a;
}
__device__ __forceinline__ void cp_async16(uint32_t dst, const void* src) {
    asm volatile("cp.async.cg.shared.global [%0], [%1], 16;" :: "r"(dst), "l"(src));
}
__device__ __forceinline__ void cp_commit() { asm volatile("cp.async.commit_group;"); }
__device__ __forceinline__ void cp_wait0()  { asm volatile("cp.async.wait_group 0;" ::: "memory"); }

__device__ __forceinline__ void ldsm4(uint32_t* r, uint32_t a) {
    asm volatile("ldmatrix.sync.aligned.m8n8.x4.shared.b16 {%0,%1,%2,%3}, [%4];"
        : "=r"(r[0]), "=r"(r[1]), "=r"(r[2]), "=r"(r[3]) : "r"(a));
}
__device__ __forceinline__ void ldsm4t(uint32_t* r, uint32_t a) {
    asm volatile("ldmatrix.sync.aligned.m8n8.x4.trans.shared.b16 {%0,%1,%2,%3}, [%4];"
        : "=r"(r[0]), "=r"(r[1]), "=r"(r[2]), "=r"(r[3]) : "r"(a));
}
__device__ __forceinline__ void mma16816(float* c, const uint32_t* a,
                                         uint32_t b0, uint32_t b1) {
    asm volatile(
        "mma.sync.aligned.m16n8k16.row.col.f32.f16.f16.f32 "
        "{%0,%1,%2,%3}, {%4,%5,%6,%7}, {%8,%9}, {%0,%1,%2,%3};"
        : "+f"(c[0]), "+f"(c[1]), "+f"(c[2]), "+f"(c[3])
        : "r"(a[0]), "r"(a[1]), "r"(a[2]), "r"(a[3]), "r"(b0), "r"(b1));
}
__device__ __forceinline__ uint32_t packf(float a, float b) {
    __half2 h = __floats2half2_rn(a, b);
    return *reinterpret_cast<uint32_t*>(&h);
}
__device__ __forceinline__ float ex2(float x) {
    float y;
    asm("ex2.approx.f32 %0, %1;" : "=f"(y) : "f"(x));
    return y;
}

// ======= precompute: K/V -> fp16 (16B stores) + per-head lambda =======
__global__ __launch_bounds__(256)
void conv_kv(const float* __restrict__ k, const float* __restrict__ v,
             const float* __restrict__ lq1, const float* __restrict__ lk1,
             const float* __restrict__ lq2, const float* __restrict__ lk2)
{
    if (blockIdx.x == 0 && threadIdx.x < NH) {
        const int h = threadIdx.x;
        float s1 = 0.f, s2 = 0.f;
        #pragma unroll 8
        for (int d = 0; d < DH; d++) {
            s1 += lq1[h * DH + d] * lk1[h * DH + d];
            s2 += lq2[h * DH + d] * lk2[h * DH + d];
        }
        g_lam[h] = __expf(s1) - __expf(s2) + LAMBDA_INIT;
    }

    const int KN8 = KN / 8, VN8 = VN / 8;
    for (int i = blockIdx.x * blockDim.x + threadIdx.x; i < KN8 + VN8;
         i += gridDim.x * blockDim.x) {
        if (i < KN8) {
            float4 x0 = ((const float4*)k)[2 * i];
            float4 x1 = ((const float4*)k)[2 * i + 1];
            uint4 o;
            o.x = packf(x0.x, x0.y); o.y = packf(x0.z, x0.w);
            o.z = packf(x1.x, x1.y); o.w = packf(x1.z, x1.w);
            ((uint4*)g_khi)[i] = o;
        } else {
            int j = i - KN8;
            float4 x0 = ((const float4*)v)[2 * j];
            float4 x1 = ((const float4*)v)[2 * j + 1];
            uint4 o;
            o.x = packf(x0.x, x0.y); o.y = packf(x0.z, x0.w);
            o.z = packf(x1.x, x1.y); o.w = packf(x1.z, x1.w);
            ((uint4*)g_vhi)[j] = o;
        }
    }
}

// ======================= attention =======================
__global__ __launch_bounds__(NT, 2)
void diff_attn_hmma13(const float* __restrict__ q,
                      const float* __restrict__ w,
                      float* __restrict__ out)
{
    extern __shared__ char smem[];
    const uint32_t sb = smem_u32(smem);

    const int qt = (int)(gridDim.x - 1u - blockIdx.x);   // big tiles first
    const int h  = blockIdx.y;
    const int b  = blockIdx.z;
    const int t    = threadIdx.x;
    const int warp = t >> 5;
    const int lane = t & 31;
    const int hd   = warp >> 2;
    const int r0   = (warp & 3) * 16;
    const int g    = lane >> 2;
    const int tq   = lane & 3;
    const int l8   = lane & 7;
    const int qq1  = (lane >> 3) & 1;
    const int qq2  = lane >> 4;
    const int wodd = warp & 1;           // phase-stagger selector

    const uint32_t a_off  = (uint32_t)((r0 + qq1 * 8 + l8) * KSTR + qq2 * 16);
    const uint32_t bk_off = (uint32_t)((qq2 * 8 + l8) * KSTR + qq1 * 16);
    const uint32_t bv_off = (uint32_t)((qq1 * 8 + l8) * VSTR + qq2 * 16);

    const size_t kbase = ((size_t)b * 2 * NH + 2 * h) * TLEN * DH;
    const size_t vbase = ((size_t)b * NH + h) * TLEN * DVV;
    const int ntiles = qt + 1;

    const char* gk1 = (const char*)g_khi + kbase * 2;
    const char* gk2 = gk1 + (size_t)TLEN * DH * 2;
    const char* gv  = (const char*)g_vhi + vbase * 2;

    // ---- prefetch stage 0 ----
    {
        const uint32_t dst = sb + OFF_STG;
        #pragma unroll
        for (int j = 0; j < 4; j++) {
            int c = t + j * NT;
            int ten = c >> 9, row = (c >> 3) & 63, col = c & 7;
            const char* src = ten ? gk2 : gk1;
            cp_async16(dst + ten * 9216 + row * KSTR + col * 16,
                       src + row * 128 + col * 16);
        }
        #pragma unroll
        for (int j = 0; j < 4; j++) {
            int c = t + j * NT;
            int row = c >> 4, col = c & 15;
            cp_async16(dst + STG_V + row * VSTR + col * 16,
                       gv + row * 256 + col * 16);
        }
        cp_commit();
    }

    // ---- Q convert (fold SCALING*log2e) ----
    {
        const float* qg1 = q + kbase + (size_t)qt * BM * DH;
        const float* qg2 = qg1 + (size_t)TLEN * DH;
        #pragma unroll
        for (int jj = 0; jj < 8; jj++) {
            int i = t + jj * NT;
            int r = i >> 5, d2 = i & 31;
            float2 x1 = ((const float2*)qg1)[i];
            *(uint32_t*)(smem + OFF_Q1 + r * KSTR + d2 * 4) =
                packf(x1.x * SCALE_L2E, x1.y * SCALE_L2E);
            float2 x2 = ((const float2*)qg2)[i];
            *(uint32_t*)(smem + OFF_Q2 + r * KSTR + d2 * 4) =
                packf(x2.x * SCALE_L2E, x2.y * SCALE_L2E);
        }
    }
    __syncthreads();

    uint32_t qf[4][4];
    {
        const uint32_t sb_q = sb + (hd ? OFF_Q2 : OFF_Q1);
        #pragma unroll
        for (int kc = 0; kc < 4; kc++)
            ldsm4(qf[kc], sb_q + kc * 32 + a_off);
    }

    float yacc[16][4];
    #pragma unroll
    for (int nt = 0; nt < 16; nt++)
        #pragma unroll
        for (int j = 0; j < 4; j++) yacc[nt][j] = 0.f;
    float l_lo = 0.f, l_hi = 0.f;

    const int rowg = qt * BM + r0 + g;
    const int rowh = rowg + 8;

    for (int kt = 0; kt < ntiles; kt++) {
        const uint32_t stg = sb + OFF_STG + (uint32_t)(kt & 1) * STG_SZ;
        cp_wait0();
        __syncthreads();

        if (kt + 1 < ntiles) {
            const uint32_t dst = sb + OFF_STG + (uint32_t)((kt + 1) & 1) * STG_SZ;
            const size_t ko = (size_t)(kt + 1) * BN * DH * 2;
            const size_t vo = (size_t)(kt + 1) * BN * DVV * 2;
            #pragma unroll
            for (int j = 0; j < 4; j++) {
                int c = t + j * NT;
                int ten = c >> 9, row = (c >> 3) & 63, col = c & 7;
                const char* src = (ten ? gk2 : gk1) + ko;
                cp_async16(dst + ten * 9216 + row * KSTR + col * 16,
                           src + row * 128 + col * 16);
            }
            #pragma unroll
            for (int j = 0; j < 4; j++) {
                int c = t + j * NT;
                int row = c >> 4, col = c & 15;
                cp_async16(dst + STG_V + row * VSTR + col * 16,
                           gv + vo + row * 256 + col * 16);
            }
            cp_commit();
        }

        const uint32_t sb_k = stg + (hd ? STG_K2 : STG_K1);
        const uint32_t sb_v = stg + STG_V;
        const int kb = kt * BN;
        const bool diag = (kt == qt);

        // ---- two 32-key halves; odd warps take half 1 first (phase stagger) ----
        #pragma unroll
        for (int hh = 0; hh < 2; hh++) {
            const int half = hh ^ wodd;
            const int kb2  = kb + half * 32;

            // QK (pipelined ldsm over kc)
            float S[4][4];
            #pragma unroll
            for (int nt = 0; nt < 4; nt++)
                #pragma unroll
                for (int j = 0; j < 4; j++) S[nt][j] = 0.f;

            #pragma unroll
            for (int aa = 0; aa < 2; aa++) {
                const int a = 2 * half + aa;
                const uint32_t base = sb_k + (uint32_t)(a * 16 * KSTR) + bk_off;
                uint32_t bh[2][4];
                ldsm4(bh[0], base);
                #pragma unroll
                for (int kc = 0; kc < 4; kc++) {
                    if (kc < 3) ldsm4(bh[(kc + 1) & 1], base + (kc + 1) * 32);
                    mma16816(S[2 * aa],     qf[kc], bh[kc & 1][0], bh[kc & 1][1]);
                    mma16816(S[2 * aa + 1], qf[kc], bh[kc & 1][2], bh[kc & 1][3]);
                }
            }

            // mask + exp2 + pack
            uint32_t Pa[4], Pb[4];
            if (diag) {
                #pragma unroll
                for (int nt = 0; nt < 4; nt++) {
                    int c0 = kb2 + nt * 8 + tq * 2;
                    float p0 = (c0     > rowg) ? 0.f : ex2(S[nt][0]);
                    float p1 = (c0 + 1 > rowg) ? 0.f : ex2(S[nt][1]);
                    float p2 = (c0     > rowh) ? 0.f : ex2(S[nt][2]);
                    float p3 = (c0 + 1 > rowh) ? 0.f : ex2(S[nt][3]);
                    l_lo += p0 + p1;  l_hi += p2 + p3;
                    Pa[nt] = packf(p0, p1);
                    Pb[nt] = packf(p2, p3);
                }
            } else {
                #pragma unroll
                for (int nt = 0; nt < 4; nt++) {
                    float p0 = ex2(S[nt][0]);
                    float p1 = ex2(S[nt][1]);
                    float p2 = ex2(S[nt][2]);
                    float p3 = ex2(S[nt][3]);
                    l_lo += p0 + p1;  l_hi += p2 + p3;
                    Pa[nt] = packf(p0, p1);
                    Pb[nt] = packf(p2, p3);
                }
            }

            // PV (non-pipelined — measured best at the 128-reg cliff)
            #pragma unroll
            for (int kc2 = 0; kc2 < 2; kc2++) {
                const int kc = 2 * half + kc2;
                uint32_t ah[4] = { Pa[2 * kc2], Pb[2 * kc2],
                                   Pa[2 * kc2 + 1], Pb[2 * kc2 + 1] };
                const uint32_t vb = sb_v + (uint32_t)(kc * 16 * VSTR) + bv_off;
                #pragma unroll
                for (int a = 0; a < 8; a++) {
                    uint32_t bh[4];
                    ldsm4t(bh, vb + a * 32);
                    mma16816(yacc[2 * a],     ah, bh[0], bh[1]);
                    mma16816(yacc[2 * a + 1], ah, bh[2], bh[3]);
                }
            }
        }
    }

    // ---- epilogue ----
    l_lo += __shfl_xor_sync(0xFFFFFFFF, l_lo, 1);
    l_lo += __shfl_xor_sync(0xFFFFFFFF, l_lo, 2);
    l_hi += __shfl_xor_sync(0xFFFFFFFF, l_hi, 1);
    l_hi += __shfl_xor_sync(0xFFFFFFFF, l_hi, 2);
    const float inv_lo = 1.f / l_lo;
    const float inv_hi = 1.f / l_hi;
    const float lam = g_lam[h];

    __syncthreads();

    float* yb = (float*)(smem + (hd ? OFF_YB2 : OFF_YB1));
    const int rg = r0 + g, rh = r0 + g + 8;
    #pragma unroll
    for (int nt = 0; nt < 16; nt++) {
        int c = nt * 8 + tq * 2;
        yb[rg * 132 + c]     = yacc[nt][0] * inv_lo;
        yb[rg * 132 + c + 1] = yacc[nt][1] * inv_lo;
        yb[rh * 132 + c]     = yacc[nt][2] * inv_hi;
        yb[rh * 132 + c + 1] = yacc[nt][3] * inv_hi;
    }
    __syncthreads();

    float* yb1 = (float*)(smem + OFF_YB1);
    float* yb2 = (float*)(smem + OFF_YB2);
    float* sp  = (float*)(smem + OFF_SP);
    float* scl = (float*)(smem + OFF_SCL);

    const int rr  = t >> 2;
    const int cc0 = (t & 3) * 32;
    float ssq = 0.f;
    #pragma unroll 8
    for (int j = 0; j < 32; j += 4) {
        float4 y1 = *(float4*)&yb1[rr * 132 + cc0 + j];
        float4 y2 = *(float4*)&yb2[rr * 132 + cc0 + j];
        float4 y;
        y.x = y1.x - lam * y2.x;  y.y = y1.y - lam * y2.y;
        y.z = y1.z - lam * y2.z;  y.w = y1.w - lam * y2.w;
        ssq += y.x * y.x + y.y * y.y + y.z * y.z + y.w * y.w;
        *(float4*)&yb1[rr * 132 + cc0 + j] = y;
    }
    sp[(t & 3) * 64 + rr] = ssq;
    __syncthreads();
    if (t < 64) {
        float tot = sp[t] + sp[64 + t] + sp[128 + t] + sp[192 + t];
        scl[t] = rsqrtf(tot * (1.f / (float)DVV) + RMS_EPS) * (1.f - LAMBDA_INIT);
    }
    __syncthreads();

    const float sc = scl[rr];
    float* og = out + (((size_t)b * NH + h) * TLEN + (size_t)qt * BM + rr) * DVV + cc0;
    #pragma unroll 8
    for (int j = 0; j < 32; j += 4) {
        float4 y = *(float4*)&yb1[rr * 132 + cc0 + j];
        float4 wv = *(const float4*)&w[cc0 + j];
        y.x *= sc * wv.x;  y.y *= sc * wv.y;
        y.z *= sc * wv.z;  y.w *= sc * wv.w;
        *(float4*)&og[j] = y;
    }
}

extern "C" void kernel_launch(void* const* d_in, const int* in_sizes, int n_in,
                              void* d_out, int out_size)
{
    const float* q   = (const float*)d_in[0];
    const float* k   = (const float*)d_in[1];
    const float* v   = (const float*)d_in[2];
    const float* lq1 = (const float*)d_in[4];
    const float* lk1 = (const float*)d_in[5];
    const float* lq2 = (const float*)d_in[6];
    const float* lk2 = (const float*)d_in[7];
    const float* w   = (const float*)d_in[8];
    float* out = (float*)d_out;

    static int attr_set = 0;
    if (!attr_set) {
        cudaFuncSetAttribute(diff_attn_hmma13,
                             cudaFuncAttributeMaxDynamicSharedMemorySize, SMEM_TOTAL);
        attr_set = 1;
    }

    conv_kv<<<2048, 256>>>(k, v, lq1, lk1, lq2, lk2);
    dim3 grid(TLEN / BM, NH, BATCH);
    diff_attn_hmma13<<<grid, NT, SMEM_TOTAL>>>(q, w, out);
}

// round 16
// speedup vs baseline: 1.0860x; 1.0573x over previous
#include <cuda_runtime.h>
#include <cuda_fp16.h>
#include <stdint.h>

#define BATCH 4
#define NH    16
#define TLEN  1024
#define DH    64
#define DVV   128
#define BM    64
#define BN    64
#define NT    256
#define SCALE_L2E 0.18033688011112042f
#define LAMBDA_INIT 0.783605766531604f
#define RMS_EPS 1e-6f

#define KSTR  144
#define VSTR  272

#define KN (BATCH * 2 * NH * TLEN * DH)
#define VN (BATCH * NH * TLEN * DVV)

__device__ __align__(16) static unsigned int g_khi[KN / 2];
__device__ __align__(16) static unsigned int g_vhi[VN / 2];
__device__ static float g_lam[NH];

#define OFF_Q1   0
#define OFF_Q2   9216
#define OFF_STG  18432
#define STG_SZ   35840
#define STG_K1   0
#define STG_K2   9216
#define STG_V    18432
#define SMEM_TOTAL 91648
#define OFF_YB1  0
#define OFF_YB2  36864

__device__ __forceinline__ uint32_t smem_u32(const void* p) {
    uint32_t a;
    asm("{ .reg .u64 t; cvta.to.shared.u64 t, %1; cvt.u32.u64 %0, t; }" : "=r"(a) : "l"(p));
    return a;
}
__device__ __forceinline__ void cp_async16(uint32_t dst, const void* src) {
    asm volatile("cp.async.cg.shared.global [%0], [%1], 16;" :: "r"(dst), "l"(src));
}
__device__ __forceinline__ void cp_commit() { asm volatile("cp.async.commit_group;"); }
__device__ __forceinline__ void cp_wait0()  { asm volatile("cp.async.wait_group 0;" ::: "memory"); }

__device__ __forceinline__ void ldsm4(uint32_t* r, uint32_t a) {
    asm volatile("ldmatrix.sync.aligned.m8n8.x4.shared.b16 {%0,%1,%2,%3}, [%4];"
        : "=r"(r[0]), "=r"(r[1]), "=r"(r[2]), "=r"(r[3]) : "r"(a));
}
__device__ __forceinline__ void ldsm4t(uint32_t* r, uint32_t a) {
    asm volatile("ldmatrix.sync.aligned.m8n8.x4.trans.shared.b16 {%0,%1,%2,%3}, [%4];"
        : "=r"(r[0]), "=r"(r[1]), "=r"(r[2]), "=r"(r[3]) : "r"(a));
}
__device__ __forceinline__ void mma16816(float* c, const uint32_t* a,
                                         uint32_t b0, uint32_t b1) {
    asm volatile(
        "mma.sync.aligned.m16n8k16.row.col.f32.f16.f16.f32 "
        "{%0,%1,%2,%3}, {%4,%5,%6,%7}, {%8,%9}, {%0,%1,%2,%3};"
        : "+f"(c[0]), "+f"(c[1]), "+f"(c[2]), "+f"(c[3])
        : "r"(a[0]), "r"(a[1]), "r"(a[2]), "r"(a[3]), "r"(b0), "r"(b1));
}
__device__ __forceinline__ uint32_t packf(float a, float b) {
    __half2 h = __floats2half2_rn(a, b);
    return *reinterpret_cast<uint32_t*>(&h);
}
__device__ __forceinline__ float ex2(float x) {
    float y;
    asm("ex2.approx.f32 %0, %1;" : "=f"(y) : "f"(x));
    return y;
}

// ======= precompute: K/V -> fp16 (16B stores) + per-head lambda =======
__global__ __launch_bounds__(256)
void conv_kv(const float* __restrict__ k, const float* __restrict__ v,
             const float* __restrict__ lq1, const float* __restrict__ lk1,
             const float* __restrict__ lq2, const float* __restrict__ lk2)
{
    if (blockIdx.x == 0 && threadIdx.x < NH) {
        const int h = threadIdx.x;
        float s1 = 0.f, s2 = 0.f;
        #pragma unroll 8
        for (int d = 0; d < DH; d++) {
            s1 += lq1[h * DH + d] * lk1[h * DH + d];
            s2 += lq2[h * DH + d] * lk2[h * DH + d];
        }
        g_lam[h] = __expf(s1) - __expf(s2) + LAMBDA_INIT;
    }

    const int KN8 = KN / 8, VN8 = VN / 8;
    for (int i = blockIdx.x * blockDim.x + threadIdx.x; i < KN8 + VN8;
         i += gridDim.x * blockDim.x) {
        if (i < KN8) {
            float4 x0 = ((const float4*)k)[2 * i];
            float4 x1 = ((const float4*)k)[2 * i + 1];
            uint4 o;
            o.x = packf(x0.x, x0.y); o.y = packf(x0.z, x0.w);
            o.z = packf(x1.x, x1.y); o.w = packf(x1.z, x1.w);
            ((uint4*)g_khi)[i] = o;
        } else {
            int j = i - KN8;
            float4 x0 = ((const float4*)v)[2 * j];
            float4 x1 = ((const float4*)v)[2 * j + 1];
            uint4 o;
            o.x = packf(x0.x, x0.y); o.y = packf(x0.z, x0.w);
            o.z = packf(x1.x, x1.y); o.w = packf(x1.z, x1.w);
            ((uint4*)g_vhi)[j] = o;
        }
    }
}

// ======================= attention =======================
__global__ __launch_bounds__(NT, 2)
void diff_attn_hmma14(const float* __restrict__ q,
                      const float* __restrict__ w,
                      float* __restrict__ out)
{
    extern __shared__ char smem[];
    const uint32_t sb = smem_u32(smem);

    const int qt = (int)(gridDim.x - 1u - blockIdx.x);   // big tiles first
    const int h  = blockIdx.y;
    const int b  = blockIdx.z;
    const int t    = threadIdx.x;
    const int warp = t >> 5;
    const int lane = t & 31;
    const int hd   = warp >> 2;
    const int r0   = (warp & 3) * 16;
    const int g    = lane >> 2;
    const int tq   = lane & 3;
    const int l8   = lane & 7;
    const int qq1  = (lane >> 3) & 1;
    const int qq2  = lane >> 4;
    const int wodd = warp & 1;           // phase-stagger selector

    const uint32_t a_off  = (uint32_t)((r0 + qq1 * 8 + l8) * KSTR + qq2 * 16);
    const uint32_t bk_off = (uint32_t)((qq2 * 8 + l8) * KSTR + qq1 * 16);
    const uint32_t bv_off = (uint32_t)((qq1 * 8 + l8) * VSTR + qq2 * 16);

    const size_t kbase = ((size_t)b * 2 * NH + 2 * h) * TLEN * DH;
    const size_t vbase = ((size_t)b * NH + h) * TLEN * DVV;
    const int ntiles = qt + 1;

    const char* gk1 = (const char*)g_khi + kbase * 2;
    const char* gk2 = gk1 + (size_t)TLEN * DH * 2;
    const char* gv  = (const char*)g_vhi + vbase * 2;

    // ---- prefetch stage 0 ----
    {
        const uint32_t dst = sb + OFF_STG;
        #pragma unroll
        for (int j = 0; j < 4; j++) {
            int c = t + j * NT;
            int ten = c >> 9, row = (c >> 3) & 63, col = c & 7;
            const char* src = ten ? gk2 : gk1;
            cp_async16(dst + ten * 9216 + row * KSTR + col * 16,
                       src + row * 128 + col * 16);
        }
        #pragma unroll
        for (int j = 0; j < 4; j++) {
            int c = t + j * NT;
            int row = c >> 4, col = c & 15;
            cp_async16(dst + STG_V + row * VSTR + col * 16,
                       gv + row * 256 + col * 16);
        }
        cp_commit();
    }

    // ---- Q convert (fold SCALING*log2e) ----
    {
        const float* qg1 = q + kbase + (size_t)qt * BM * DH;
        const float* qg2 = qg1 + (size_t)TLEN * DH;
        #pragma unroll
        for (int jj = 0; jj < 8; jj++) {
            int i = t + jj * NT;
            int r = i >> 5, d2 = i & 31;
            float2 x1 = ((const float2*)qg1)[i];
            *(uint32_t*)(smem + OFF_Q1 + r * KSTR + d2 * 4) =
                packf(x1.x * SCALE_L2E, x1.y * SCALE_L2E);
            float2 x2 = ((const float2*)qg2)[i];
            *(uint32_t*)(smem + OFF_Q2 + r * KSTR + d2 * 4) =
                packf(x2.x * SCALE_L2E, x2.y * SCALE_L2E);
        }
    }
    __syncthreads();

    uint32_t qf[4][4];
    {
        const uint32_t sb_q = sb + (hd ? OFF_Q2 : OFF_Q1);
        #pragma unroll
        for (int kc = 0; kc < 4; kc++)
            ldsm4(qf[kc], sb_q + kc * 32 + a_off);
    }

    float yacc[16][4];
    #pragma unroll
    for (int nt = 0; nt < 16; nt++)
        #pragma unroll
        for (int j = 0; j < 4; j++) yacc[nt][j] = 0.f;
    float l_lo = 0.f, l_hi = 0.f;

    const int rowg = qt * BM + r0 + g;
    const int rowh = rowg + 8;

    for (int kt = 0; kt < ntiles; kt++) {
        const uint32_t stg = sb + OFF_STG + (uint32_t)(kt & 1) * STG_SZ;
        cp_wait0();
        __syncthreads();

        if (kt + 1 < ntiles) {
            const uint32_t dst = sb + OFF_STG + (uint32_t)((kt + 1) & 1) * STG_SZ;
            const size_t ko = (size_t)(kt + 1) * BN * DH * 2;
            const size_t vo = (size_t)(kt + 1) * BN * DVV * 2;
            #pragma unroll
            for (int j = 0; j < 4; j++) {
                int c = t + j * NT;
                int ten = c >> 9, row = (c >> 3) & 63, col = c & 7;
                const char* src = (ten ? gk2 : gk1) + ko;
                cp_async16(dst + ten * 9216 + row * KSTR + col * 16,
                           src + row * 128 + col * 16);
            }
            #pragma unroll
            for (int j = 0; j < 4; j++) {
                int c = t + j * NT;
                int row = c >> 4, col = c & 15;
                cp_async16(dst + STG_V + row * VSTR + col * 16,
                           gv + vo + row * 256 + col * 16);
            }
            cp_commit();
        }

        const uint32_t sb_k = stg + (hd ? STG_K2 : STG_K1);
        const uint32_t sb_v = stg + STG_V;
        const int kb = kt * BN;
        const bool diag = (kt == qt);

        // ---- two 32-key halves; odd warps take half 1 first (phase stagger) ----
        #pragma unroll
        for (int hh = 0; hh < 2; hh++) {
            const int half = hh ^ wodd;
            const int kb2  = kb + half * 32;

            // QK (pipelined ldsm over kc)
            float S[4][4];
            #pragma unroll
            for (int nt = 0; nt < 4; nt++)
                #pragma unroll
                for (int j = 0; j < 4; j++) S[nt][j] = 0.f;

            #pragma unroll
            for (int aa = 0; aa < 2; aa++) {
                const int a = 2 * half + aa;
                const uint32_t base = sb_k + (uint32_t)(a * 16 * KSTR) + bk_off;
                uint32_t bh[2][4];
                ldsm4(bh[0], base);
                #pragma unroll
                for (int kc = 0; kc < 4; kc++) {
                    if (kc < 3) ldsm4(bh[(kc + 1) & 1], base + (kc + 1) * 32);
                    mma16816(S[2 * aa],     qf[kc], bh[kc & 1][0], bh[kc & 1][1]);
                    mma16816(S[2 * aa + 1], qf[kc], bh[kc & 1][2], bh[kc & 1][3]);
                }
            }

            // mask + exp2 + pack
            uint32_t Pa[4], Pb[4];
            if (diag) {
                #pragma unroll
                for (int nt = 0; nt < 4; nt++) {
                    int c0 = kb2 + nt * 8 + tq * 2;
                    float p0 = (c0     > rowg) ? 0.f : ex2(S[nt][0]);
                    float p1 = (c0 + 1 > rowg) ? 0.f : ex2(S[nt][1]);
                    float p2 = (c0     > rowh) ? 0.f : ex2(S[nt][2]);
                    float p3 = (c0 + 1 > rowh) ? 0.f : ex2(S[nt][3]);
                    l_lo += p0 + p1;  l_hi += p2 + p3;
                    Pa[nt] = packf(p0, p1);
                    Pb[nt] = packf(p2, p3);
                }
            } else {
                #pragma unroll
                for (int nt = 0; nt < 4; nt++) {
                    float p0 = ex2(S[nt][0]);
                    float p1 = ex2(S[nt][1]);
                    float p2 = ex2(S[nt][2]);
                    float p3 = ex2(S[nt][3]);
                    l_lo += p0 + p1;  l_hi += p2 + p3;
                    Pa[nt] = packf(p0, p1);
                    Pb[nt] = packf(p2, p3);
                }
            }

            // PV (non-pipelined — measured best at the 128-reg cliff)
            #pragma unroll
            for (int kc2 = 0; kc2 < 2; kc2++) {
                const int kc = 2 * half + kc2;
                uint32_t ah[4] = { Pa[2 * kc2], Pb[2 * kc2],
                                   Pa[2 * kc2 + 1], Pb[2 * kc2 + 1] };
                const uint32_t vb = sb_v + (uint32_t)(kc * 16 * VSTR) + bv_off;
                #pragma unroll
                for (int a = 0; a < 8; a++) {
                    uint32_t bh[4];
                    ldsm4t(bh, vb + a * 32);
                    mma16816(yacc[2 * a],     ah, bh[0], bh[1]);
                    mma16816(yacc[2 * a + 1], ah, bh[2], bh[3]);
                }
            }
        }
    }

    // ---- epilogue ----
    l_lo += __shfl_xor_sync(0xFFFFFFFF, l_lo, 1);
    l_lo += __shfl_xor_sync(0xFFFFFFFF, l_lo, 2);
    l_hi += __shfl_xor_sync(0xFFFFFFFF, l_hi, 1);
    l_hi += __shfl_xor_sync(0xFFFFFFFF, l_hi, 2);
    const float inv_lo = 1.f / l_lo;
    const float inv_hi = 1.f / l_hi;
    const float lam = g_lam[h];

    __syncthreads();

    float* yb = (float*)(smem + (hd ? OFF_YB2 : OFF_YB1));
    const int rg = r0 + g, rh = r0 + g + 8;
    #pragma unroll
    for (int nt = 0; nt < 16; nt++) {
        int c = nt * 8 + tq * 2;
        yb[rg * 132 + c]     = yacc[nt][0] * inv_lo;
        yb[rg * 132 + c + 1] = yacc[nt][1] * inv_lo;
        yb[rh * 132 + c]     = yacc[nt][2] * inv_hi;
        yb[rh * 132 + c + 1] = yacc[nt][3] * inv_hi;
    }
    __syncthreads();

    float* yb1 = (float*)(smem + OFF_YB1);
    float* yb2 = (float*)(smem + OFF_YB2);

    // row rr handled by 4 consecutive lanes (t = 4*rr + {0..3}) -> shfl reduce
    const int rr  = t >> 2;
    const int cc0 = (t & 3) * 32;
    float yv[32];
    float ssq = 0.f;
    #pragma unroll 8
    for (int j = 0; j < 32; j += 4) {
        float4 y1 = *(float4*)&yb1[rr * 132 + cc0 + j];
        float4 y2 = *(float4*)&yb2[rr * 132 + cc0 + j];
        float4 y;
        y.x = y1.x - lam * y2.x;  y.y = y1.y - lam * y2.y;
        y.z = y1.z - lam * y2.z;  y.w = y1.w - lam * y2.w;
        ssq += y.x * y.x + y.y * y.y + y.z * y.z + y.w * y.w;
        yv[j] = y.x; yv[j + 1] = y.y; yv[j + 2] = y.z; yv[j + 3] = y.w;
    }
    ssq += __shfl_xor_sync(0xFFFFFFFF, ssq, 1);
    ssq += __shfl_xor_sync(0xFFFFFFFF, ssq, 2);
    const float sc = rsqrtf(ssq * (1.f / (float)DVV) + RMS_EPS) * (1.f - LAMBDA_INIT);

    float* og = out + (((size_t)b * NH + h) * TLEN + (size_t)qt * BM + rr) * DVV + cc0;
    #pragma unroll 8
    for (int j = 0; j < 32; j += 4) {
        float4 wv = *(const float4*)&w[cc0 + j];
        float4 o;
        o.x = yv[j]     * sc * wv.x;
        o.y = yv[j + 1] * sc * wv.y;
        o.z = yv[j + 2] * sc * wv.z;
        o.w = yv[j + 3] * sc * wv.w;
        *(float4*)&og[j] = o;
    }
}

extern "C" void kernel_launch(void* const* d_in, const int* in_sizes, int n_in,
                              void* d_out, int out_size)
{
    const float* q   = (const float*)d_in[0];
    const float* k   = (const float*)d_in[1];
    const float* v   = (const float*)d_in[2];
    const float* lq1 = (const float*)d_in[4];
    const float* lk1 = (const float*)d_in[5];
    const float* lq2 = (const float*)d_in[6];
    const float* lk2 = (const float*)d_in[7];
    const float* w   = (const float*)d_in[8];
    float* out = (float*)d_out;

    static int attr_set = 0;
    if (!attr_set) {
        cudaFuncSetAttribute(diff_attn_hmma14,
                             cudaFuncAttributeMaxDynamicSharedMemorySize, SMEM_TOTAL);
        attr_set = 1;
    }

    conv_kv<<<2048, 256>>>(k, v, lq1, lk1, lq2, lk2);
    dim3 grid(TLEN / BM, NH, BATCH);
    diff_attn_hmma14<<<grid, NT, SMEM_TOTAL>>>(q, w, out);
}